// round 1
// baseline (speedup 1.0000x reference)
#include <cuda_runtime.h>
#include <cuda_bf16.h>
#include <math.h>

#define D_MODEL 1024
#define NHEAD   16
#define DH      64
#define D_FF    4096
#define SEQ     2048
#define BATCH   2
#define NTOK    (SEQ * BATCH)   // 4096 rows
#define EPS     1e-5f

// ---------------- scratch (static device globals; no allocation allowed) ----
__device__ float g_XB [NTOK * D_MODEL];   // x transposed to [B*S, D]
__device__ float g_Q  [NTOK * D_MODEL];
__device__ float g_K  [NTOK * D_MODEL];
__device__ float g_V  [NTOK * D_MODEL];
__device__ float g_CTX[NTOK * D_MODEL];
__device__ float g_T1 [NTOK * D_MODEL];
__device__ float g_X1 [NTOK * D_MODEL];
__device__ float g_H  [NTOK * D_FF   ];
__device__ float g_T2 [NTOK * D_MODEL];

// ---------------- transpose [S,B,D] -> [B*S, D] ----------------------------
__global__ void transpose_in_kernel(const float* __restrict__ x, float* __restrict__ xb)
{
    int idx = blockIdx.x * 256 + threadIdx.x;      // one float4 each; 4096*256 total
    int r  = idx >> 8;                             // row in [0, 4096)
    int c4 = idx & 255;                            // float4 column
    int b_ = r / SEQ;
    int s_ = r - b_ * SEQ;
    ((float4*)xb)[idx] = ((const float4*)x)[(size_t)(s_ * BATCH + b_) * 256 + c4];
}

// ---------------- SGEMM 128x128x8, 8x8 per thread, fused epilogue ----------
// epi: 0 = +bias, 1 = +bias then exact GELU, 2 = +bias +residual
__global__ __launch_bounds__(256, 2)
void sgemm_kernel(const float* __restrict__ A, const float* __restrict__ Bm,
                  const float* __restrict__ bias, const float* __restrict__ Res,
                  float* __restrict__ C, int M, int N, int K, int epi)
{
    __shared__ float As[8][128];
    __shared__ float Bs[8][128];

    const int tid  = threadIdx.x;
    const int brow = blockIdx.y * 128;
    const int bcol = blockIdx.x * 128;

    const int arow = tid >> 1;             // 0..127
    const int acol = (tid & 1) * 4;        // 0 or 4
    const int browl = tid >> 5;            // 0..7
    const int bcoll = (tid & 31) * 4;      // 0..124

    const float* Aptr = A + (size_t)(brow + arow) * K + acol;
    const float* Bptr = Bm + (size_t)browl * N + bcol + bcoll;

    float acc[8][8];
#pragma unroll
    for (int i = 0; i < 8; i++)
#pragma unroll
        for (int j = 0; j < 8; j++) acc[i][j] = 0.f;

    const int ty = (tid >> 4) * 8;
    const int tx = (tid & 15) * 8;

    for (int k0 = 0; k0 < K; k0 += 8) {
        float4 av = *(const float4*)Aptr;  Aptr += 8;
        float4 bv = *(const float4*)Bptr;  Bptr += (size_t)8 * N;

        As[acol + 0][arow] = av.x;
        As[acol + 1][arow] = av.y;
        As[acol + 2][arow] = av.z;
        As[acol + 3][arow] = av.w;
        *(float4*)&Bs[browl][bcoll] = bv;
        __syncthreads();

#pragma unroll
        for (int kk = 0; kk < 8; kk++) {
            float4 a0 = *(float4*)&As[kk][ty];
            float4 a1 = *(float4*)&As[kk][ty + 4];
            float4 b0 = *(float4*)&Bs[kk][tx];
            float4 b1 = *(float4*)&Bs[kk][tx + 4];
            float a[8] = {a0.x,a0.y,a0.z,a0.w,a1.x,a1.y,a1.z,a1.w};
            float b[8] = {b0.x,b0.y,b0.z,b0.w,b1.x,b1.y,b1.z,b1.w};
#pragma unroll
            for (int i = 0; i < 8; i++)
#pragma unroll
                for (int j = 0; j < 8; j++)
                    acc[i][j] += a[i] * b[j];
        }
        __syncthreads();
    }

    // epilogue
    float bj[8];
#pragma unroll
    for (int j = 0; j < 8; j++) bj[j] = bias[bcol + tx + j];

#pragma unroll
    for (int i = 0; i < 8; i++) {
        size_t r = (size_t)(brow + ty + i);
        float v[8];
#pragma unroll
        for (int j = 0; j < 8; j++) {
            float vv = acc[i][j] + bj[j];
            if (epi == 1) vv = 0.5f * vv * (1.f + erff(vv * 0.70710678118654752f));
            v[j] = vv;
        }
        if (epi == 2) {
            const float* rp = Res + r * N + bcol + tx;
            float4 r0 = *(const float4*)rp;
            float4 r1 = *(const float4*)(rp + 4);
            v[0]+=r0.x; v[1]+=r0.y; v[2]+=r0.z; v[3]+=r0.w;
            v[4]+=r1.x; v[5]+=r1.y; v[6]+=r1.z; v[7]+=r1.w;
        }
        float* cp = C + r * N + bcol + tx;
        *(float4*)cp       = make_float4(v[0], v[1], v[2], v[3]);
        *(float4*)(cp + 4) = make_float4(v[4], v[5], v[6], v[7]);
    }
}

// ---------------- fused flash attention (fp32) -----------------------------
// grid: (32 q-tiles, B*H=32).  block: 256 threads.
// smem: Qs[64][64] | Ps[64][64] | KVs[64][68]
#define ATT_SMEM_FLOATS (64*64 + 64*64 + 64*68)
#define ATT_SMEM_BYTES  (ATT_SMEM_FLOATS * 4)

__global__ __launch_bounds__(256, 2)
void attention_kernel(const float* __restrict__ Qg, const float* __restrict__ Kg,
                      const float* __restrict__ Vg, float* __restrict__ Og)
{
    extern __shared__ float sm[];
    float* Qs  = sm;            // 4096
    float* Ps  = sm + 4096;     // 4096
    float* KVs = sm + 8192;     // 64*68

    const int tid = threadIdx.x;
    const int qt  = blockIdx.x;           // q tile
    const int bh  = blockIdx.y;
    const int b_  = bh >> 4;
    const int h_  = bh & 15;

    const size_t baseQ  = ((size_t)(b_ * SEQ + qt * 64)) * D_MODEL + h_ * DH;
    const size_t baseKV = ((size_t)(b_ * SEQ)) * D_MODEL + h_ * DH;

    // load Q tile (64 x 64)
    for (int i = tid; i < 1024; i += 256) {
        int r = i >> 4, c4 = (i & 15) * 4;
        *(float4*)(Qs + r * 64 + c4) = *(const float4*)(Qg + baseQ + (size_t)r * D_MODEL + c4);
    }

    const int qi = (tid >> 4) * 4;   // this thread's 4 query rows
    const int kj = (tid & 15) * 4;   // this thread's 4 key cols / 4 dv cols

    float m_i[4], l_i[4], acc[4][4];
#pragma unroll
    for (int i = 0; i < 4; i++) {
        m_i[i] = -INFINITY; l_i[i] = 0.f;
#pragma unroll
        for (int j = 0; j < 4; j++) acc[i][j] = 0.f;
    }

    for (int kt = 0; kt < 32; kt++) {
        __syncthreads();   // prior PV reads of Ps/KVs done
        // K tile -> KVs
        for (int i = tid; i < 1024; i += 256) {
            int r = i >> 4, c4 = (i & 15) * 4;
            *(float4*)(KVs + r * 68 + c4) =
                *(const float4*)(Kg + baseKV + (size_t)(kt * 64 + r) * D_MODEL + c4);
        }
        __syncthreads();

        // scores: s[i][j] = sum_d Qs[qi+i][d] * KVs[kj+j][d]
        float s[4][4];
#pragma unroll
        for (int i = 0; i < 4; i++)
#pragma unroll
            for (int j = 0; j < 4; j++) s[i][j] = 0.f;

#pragma unroll
        for (int d = 0; d < 64; d += 4) {
            float4 a[4], bv[4];
#pragma unroll
            for (int i = 0; i < 4; i++) a[i]  = *(float4*)(Qs  + (qi + i) * 64 + d);
#pragma unroll
            for (int j = 0; j < 4; j++) bv[j] = *(float4*)(KVs + (kj + j) * 68 + d);
#pragma unroll
            for (int i = 0; i < 4; i++)
#pragma unroll
                for (int j = 0; j < 4; j++)
                    s[i][j] += a[i].x*bv[j].x + a[i].y*bv[j].y + a[i].z*bv[j].z + a[i].w*bv[j].w;
        }

        // online softmax (reduce across the 16 lanes sharing these q rows)
#pragma unroll
        for (int i = 0; i < 4; i++) {
            float mx = -INFINITY;
#pragma unroll
            for (int j = 0; j < 4; j++) { s[i][j] *= 0.125f; mx = fmaxf(mx, s[i][j]); }
#pragma unroll
            for (int o = 8; o >= 1; o >>= 1) mx = fmaxf(mx, __shfl_xor_sync(0xffffffffu, mx, o));
            float mnew = fmaxf(m_i[i], mx);
            float f    = __expf(m_i[i] - mnew);
            float rs   = 0.f;
#pragma unroll
            for (int j = 0; j < 4; j++) { float p = __expf(s[i][j] - mnew); s[i][j] = p; rs += p; }
#pragma unroll
            for (int o = 8; o >= 1; o >>= 1) rs += __shfl_xor_sync(0xffffffffu, rs, o);
            l_i[i] = l_i[i] * f + rs;
            m_i[i] = mnew;
#pragma unroll
            for (int j = 0; j < 4; j++) acc[i][j] *= f;
        }

        // stage P
#pragma unroll
        for (int i = 0; i < 4; i++)
            *(float4*)(Ps + (qi + i) * 64 + kj) = make_float4(s[i][0], s[i][1], s[i][2], s[i][3]);
        __syncthreads();

        // V tile -> KVs (overwrite K)
        for (int i = tid; i < 1024; i += 256) {
            int r = i >> 4, c4 = (i & 15) * 4;
            *(float4*)(KVs + r * 68 + c4) =
                *(const float4*)(Vg + baseKV + (size_t)(kt * 64 + r) * D_MODEL + c4);
        }
        __syncthreads();

        // acc[i][j] += sum_k Ps[qi+i][k] * V[k][kj+j]
#pragma unroll
        for (int k = 0; k < 64; k += 4) {
            float4 a[4];
#pragma unroll
            for (int i = 0; i < 4; i++) a[i] = *(float4*)(Ps + (qi + i) * 64 + k);
#pragma unroll
            for (int kk = 0; kk < 4; kk++) {
                float4 bv = *(float4*)(KVs + (k + kk) * 68 + kj);
#pragma unroll
                for (int i = 0; i < 4; i++) {
                    float av = (kk == 0) ? a[i].x : (kk == 1) ? a[i].y : (kk == 2) ? a[i].z : a[i].w;
                    acc[i][0] += av * bv.x;
                    acc[i][1] += av * bv.y;
                    acc[i][2] += av * bv.z;
                    acc[i][3] += av * bv.w;
                }
            }
        }
    }

    // write ctx
#pragma unroll
    for (int i = 0; i < 4; i++) {
        float inv = 1.f / l_i[i];
        float* op = Og + ((size_t)(b_ * SEQ + qt * 64 + qi + i)) * D_MODEL + h_ * DH + kj;
        *(float4*)op = make_float4(acc[i][0] * inv, acc[i][1] * inv, acc[i][2] * inv, acc[i][3] * inv);
    }
}

// ---------------- layernorm (one block / row) -------------------------------
__global__ void layernorm_kernel(const float* __restrict__ in, const float* __restrict__ g,
                                 const float* __restrict__ be, float* __restrict__ out,
                                 int transpose_out)
{
    __shared__ float rs[8], rq[8];
    const int row = blockIdx.x;
    const int tid = threadIdx.x;            // 256 threads, 4 floats each

    float4 v = ((const float4*)(in + (size_t)row * D_MODEL))[tid];
    float s = v.x + v.y + v.z + v.w;
    float q = v.x*v.x + v.y*v.y + v.z*v.z + v.w*v.w;
#pragma unroll
    for (int o = 16; o >= 1; o >>= 1) {
        s += __shfl_xor_sync(0xffffffffu, s, o);
        q += __shfl_xor_sync(0xffffffffu, q, o);
    }
    if ((tid & 31) == 0) { rs[tid >> 5] = s; rq[tid >> 5] = q; }
    __syncthreads();
    s = 0.f; q = 0.f;
#pragma unroll
    for (int i = 0; i < 8; i++) { s += rs[i]; q += rq[i]; }

    float mean = s * (1.f / D_MODEL);
    float var  = q * (1.f / D_MODEL) - mean * mean;
    float rstd = rsqrtf(var + EPS);

    float4 g4 = ((const float4*)g)[tid];
    float4 b4 = ((const float4*)be)[tid];
    float4 o4;
    o4.x = (v.x - mean) * rstd * g4.x + b4.x;
    o4.y = (v.y - mean) * rstd * g4.y + b4.y;
    o4.z = (v.z - mean) * rstd * g4.z + b4.z;
    o4.w = (v.w - mean) * rstd * g4.w + b4.w;

    size_t orow = row;
    if (transpose_out) {
        int b_ = row >> 11;          // row / SEQ  (SEQ = 2048)
        int s_ = row & 2047;
        orow = (size_t)s_ * BATCH + b_;
    }
    ((float4*)(out + orow * D_MODEL))[tid] = o4;
}

// ---------------- launch ----------------------------------------------------
extern "C" void kernel_launch(void* const* d_in, const int* in_sizes, int n_in,
                              void* d_out, int out_size)
{
    const float* x   = (const float*)d_in[0];
    const float* Wq  = (const float*)d_in[1];
    const float* bq  = (const float*)d_in[2];
    const float* Wk  = (const float*)d_in[3];
    const float* bk  = (const float*)d_in[4];
    const float* Wv  = (const float*)d_in[5];
    const float* bv  = (const float*)d_in[6];
    const float* Wo  = (const float*)d_in[7];
    const float* bo  = (const float*)d_in[8];
    const float* W1  = (const float*)d_in[9];
    const float* b1  = (const float*)d_in[10];
    const float* W2  = (const float*)d_in[11];
    const float* b2  = (const float*)d_in[12];
    const float* g1  = (const float*)d_in[13];
    const float* be1 = (const float*)d_in[14];
    const float* g2  = (const float*)d_in[15];
    const float* be2 = (const float*)d_in[16];
    float* out = (float*)d_out;

    float *XB, *Q, *K, *V, *CTX, *T1, *X1, *H, *T2;
    cudaGetSymbolAddress((void**)&XB,  g_XB);
    cudaGetSymbolAddress((void**)&Q,   g_Q);
    cudaGetSymbolAddress((void**)&K,   g_K);
    cudaGetSymbolAddress((void**)&V,   g_V);
    cudaGetSymbolAddress((void**)&CTX, g_CTX);
    cudaGetSymbolAddress((void**)&T1,  g_T1);
    cudaGetSymbolAddress((void**)&X1,  g_X1);
    cudaGetSymbolAddress((void**)&H,   g_H);
    cudaGetSymbolAddress((void**)&T2,  g_T2);

    cudaFuncSetAttribute(attention_kernel,
                         cudaFuncAttributeMaxDynamicSharedMemorySize, ATT_SMEM_BYTES);

    // 1) transpose x -> XB
    transpose_in_kernel<<<4096, 256>>>(x, XB);

    // 2) QKV projections
    dim3 gP(D_MODEL / 128, NTOK / 128);   // (8, 32)
    sgemm_kernel<<<gP, 256>>>(XB, Wq, bq, nullptr, Q, NTOK, D_MODEL, D_MODEL, 0);
    sgemm_kernel<<<gP, 256>>>(XB, Wk, bk, nullptr, K, NTOK, D_MODEL, D_MODEL, 0);
    sgemm_kernel<<<gP, 256>>>(XB, Wv, bv, nullptr, V, NTOK, D_MODEL, D_MODEL, 0);

    // 3) attention
    attention_kernel<<<dim3(SEQ / 64, BATCH * NHEAD), 256, ATT_SMEM_BYTES>>>(Q, K, V, CTX);

    // 4) O-proj + residual, then LN1
    sgemm_kernel<<<gP, 256>>>(CTX, Wo, bo, XB, T1, NTOK, D_MODEL, D_MODEL, 2);
    layernorm_kernel<<<NTOK, 256>>>(T1, g1, be1, X1, 0);

    // 5) FFN
    dim3 gF1(D_FF / 128, NTOK / 128);     // (32, 32)
    sgemm_kernel<<<gF1, 256>>>(X1, W1, b1, nullptr, H, NTOK, D_FF, D_MODEL, 1);
    sgemm_kernel<<<gP, 256>>>(H, W2, b2, X1, T2, NTOK, D_MODEL, D_FF, 2);

    // 6) LN2 + transpose back to [S,B,D]
    layernorm_kernel<<<NTOK, 256>>>(T2, g2, be2, out, 1);
}

// round 3
// speedup vs baseline: 1.5842x; 1.5842x over previous
#include <cuda_runtime.h>
#include <cuda_bf16.h>
#include <cuda.h>
#include <math.h>
#include <stdint.h>

#define D_MODEL 1024
#define NHEAD   16
#define DH      64
#define D_FF    4096
#define SEQ     2048
#define BATCH   2
#define NTOK    (SEQ * BATCH)
#define EPS     1e-5f
#define QKV_N   (3 * D_MODEL)   // 3072

// ======================= helpers ============================================
__device__ __forceinline__ uint32_t smem_to_u32(const void* p) {
    uint32_t a;
    asm("{ .reg .u64 t; cvta.to.shared.u64 t, %1; cvt.u32.u64 %0, t; }" : "=r"(a) : "l"(p));
    return a;
}
__device__ __forceinline__ void cp_async16(uint32_t dst, const void* src) {
    asm volatile("cp.async.cg.shared.global [%0], [%1], 16;" :: "r"(dst), "l"(src) : "memory");
}
#define CP_COMMIT() asm volatile("cp.async.commit_group;" ::: "memory")
#define CP_WAIT(n)  asm volatile("cp.async.wait_group %0;" :: "n"(n) : "memory")

__device__ __forceinline__ void ldm_x4(uint32_t* r, uint32_t addr) {
    asm volatile("ldmatrix.sync.aligned.m8n8.x4.shared.b16 {%0,%1,%2,%3}, [%4];"
        : "=r"(r[0]), "=r"(r[1]), "=r"(r[2]), "=r"(r[3]) : "r"(addr));
}
__device__ __forceinline__ void ldm_x2(uint32_t* r, uint32_t addr) {
    asm volatile("ldmatrix.sync.aligned.m8n8.x2.shared.b16 {%0,%1}, [%2];"
        : "=r"(r[0]), "=r"(r[1]) : "r"(addr));
}
__device__ __forceinline__ void mma_bf16(float* d, const uint32_t* a, const uint32_t* b) {
    asm volatile("mma.sync.aligned.m16n8k16.row.col.f32.bf16.bf16.f32 "
        "{%0,%1,%2,%3}, {%4,%5,%6,%7}, {%8,%9}, {%0,%1,%2,%3};"
        : "+f"(d[0]), "+f"(d[1]), "+f"(d[2]), "+f"(d[3])
        : "r"(a[0]), "r"(a[1]), "r"(a[2]), "r"(a[3]), "r"(b[0]), "r"(b[1]));
}
__device__ __forceinline__ void split2(float x, __nv_bfloat16& h, __nv_bfloat16& l) {
    h = __float2bfloat16_rn(x);
    l = __float2bfloat16_rn(x - __bfloat162float(h));
}

// ======================= scratch ============================================
__device__ float          g_XB  [NTOK * D_MODEL];
__device__ __nv_bfloat16  g_XBh [NTOK * D_MODEL];
__device__ __nv_bfloat16  g_XBl [NTOK * D_MODEL];
__device__ float          g_QKV [NTOK * QKV_N];
__device__ __nv_bfloat16  g_CTXh[NTOK * D_MODEL];
__device__ __nv_bfloat16  g_CTXl[NTOK * D_MODEL];
__device__ float          g_T1  [NTOK * D_MODEL];
__device__ float          g_X1  [NTOK * D_MODEL];
__device__ __nv_bfloat16  g_X1h [NTOK * D_MODEL];
__device__ __nv_bfloat16  g_X1l [NTOK * D_MODEL];
__device__ __nv_bfloat16  g_Hh  [NTOK * D_FF];
__device__ __nv_bfloat16  g_Hl  [NTOK * D_FF];
__device__ float          g_T2  [NTOK * D_MODEL];
__device__ __nv_bfloat16  g_Wqkvth[QKV_N * D_MODEL];
__device__ __nv_bfloat16  g_Wqkvtl[QKV_N * D_MODEL];
__device__ __nv_bfloat16  g_Woth[D_MODEL * D_MODEL];
__device__ __nv_bfloat16  g_Wotl[D_MODEL * D_MODEL];
__device__ __nv_bfloat16  g_W1th[D_FF * D_MODEL];
__device__ __nv_bfloat16  g_W1tl[D_FF * D_MODEL];
__device__ __nv_bfloat16  g_W2th[D_MODEL * D_FF];
__device__ __nv_bfloat16  g_W2tl[D_MODEL * D_FF];
__device__ float          g_bqkv[QKV_N];

// ======================= prep kernels =======================================
__global__ void transpose_in_kernel(const float* __restrict__ x, float* __restrict__ xb,
                                    __nv_bfloat16* __restrict__ xh, __nv_bfloat16* __restrict__ xl)
{
    int idx = blockIdx.x * 256 + threadIdx.x;
    int r  = idx >> 8;
    int c4 = idx & 255;
    int b_ = r / SEQ;
    int s_ = r - b_ * SEQ;
    float4 v = ((const float4*)x)[(size_t)(s_ * BATCH + b_) * 256 + c4];
    ((float4*)xb)[idx] = v;
    __nv_bfloat16 h0,l0,h1,l1,h2,l2,h3,l3;
    split2(v.x,h0,l0); split2(v.y,h1,l1); split2(v.z,h2,l2); split2(v.w,h3,l3);
    __nv_bfloat162* ph = (__nv_bfloat162*)(xh + (size_t)idx * 4);
    __nv_bfloat162* pl = (__nv_bfloat162*)(xl + (size_t)idx * 4);
    ph[0] = __nv_bfloat162(h0, h1); ph[1] = __nv_bfloat162(h2, h3);
    pl[0] = __nv_bfloat162(l0, l1); pl[1] = __nv_bfloat162(l2, l3);
}

__global__ void transpose_split_kernel(const float* __restrict__ W, int K, int N,
                                       __nv_bfloat16* __restrict__ Oh, __nv_bfloat16* __restrict__ Ol)
{
    __shared__ float t[32][33];
    int n0 = blockIdx.x * 32, k0 = blockIdx.y * 32;
    int tx = threadIdx.x, ty = threadIdx.y;     // (32, 8)
#pragma unroll
    for (int i = 0; i < 4; i++)
        t[ty + 8*i][tx] = W[(size_t)(k0 + ty + 8*i) * N + n0 + tx];
    __syncthreads();
#pragma unroll
    for (int i = 0; i < 4; i++) {
        float v = t[tx][ty + 8*i];
        __nv_bfloat16 h, l; split2(v, h, l);
        size_t o = (size_t)(n0 + ty + 8*i) * K + k0 + tx;
        Oh[o] = h; Ol[o] = l;
    }
}

__global__ void concat_bias_kernel(const float* bq, const float* bk, const float* bv, float* o)
{
    int i = blockIdx.x * 256 + threadIdx.x;
    if (i < QKV_N) {
        const float* s = (i < 1024) ? bq : (i < 2048) ? bk : bv;
        o[i] = s[i & 1023];
    }
}

// ======================= HMMA bf16x3 GEMM ===================================
// C[M,N] = A[M,K] * Bt[N,K]^T ; A,Bt as bf16 hi/lo.
// epi 0: +bias -> Cf ; 1: +bias,GELU -> Ch,Cl ; 2: +bias +Res -> Cf
// CTA tile 128x128, 8 warps (2m x 4n), warp tile 64x32, K-chunk 32.
// smem: per stage 4 parts (Ah, Al, Bh, Bl) each 128 rows x 80B (32 bf16 + pad).
#define GK        32
#define ROWB      80
#define PARTB     (128 * ROWB)       // 10240
#define STAGEB    (4 * PARTB)        // 40960
#define GEMM_SMEM (2 * STAGEB)       // 81920

__global__ __launch_bounds__(256)
void gemm_hmma_kernel(const __nv_bfloat16* __restrict__ Ah, const __nv_bfloat16* __restrict__ Al,
                      const __nv_bfloat16* __restrict__ Bth, const __nv_bfloat16* __restrict__ Btl,
                      const float* __restrict__ bias, const float* __restrict__ Res,
                      float* __restrict__ Cf, __nv_bfloat16* __restrict__ Ch, __nv_bfloat16* __restrict__ Cl,
                      int K, int N, int epi)
{
    extern __shared__ char smem[];
    const uint32_t sbase = smem_to_u32(smem);

    const int tid = threadIdx.x;
    const int wid = tid >> 5;
    const int lid = tid & 31;
    const int wm = wid >> 2;         // 0..1 -> m offset 64*wm
    const int wn = wid & 3;          // 0..3 -> n offset 32*wn
    const int brow = blockIdx.y * 128;
    const int bcol = blockIdx.x * 128;
    const int NC = K / GK;

    float acc[4][4][4];
#pragma unroll
    for (int mi = 0; mi < 4; mi++)
#pragma unroll
        for (int ni = 0; ni < 4; ni++)
#pragma unroll
            for (int e = 0; e < 4; e++) acc[mi][ni][e] = 0.f;

    // ---- loader: 2048 x 16B per chunk (4 parts x 128 rows x 2 vec) ----
    // i = tid + p*256, p<8 ; part = i>>9 ; j = i&511 ; r = j>>2 ; c = j&3
    auto load_chunk = [&](int kc, int s) {
        const int kb = kc * GK;
        const __nv_bfloat16* srcs[4] = { Ah, Al, Bth, Btl };
#pragma unroll
        for (int p = 0; p < 8; p++) {
            int i = tid + p * 256;
            int part = i >> 9;
            int j = i & 511;
            int r = j >> 2, c = j & 3;
            int grow = ((part < 2) ? brow : bcol) + r;
            const __nv_bfloat16* src = srcs[part] + (size_t)grow * K + kb + c * 8;
            cp_async16(sbase + s * STAGEB + part * PARTB + r * ROWB + c * 16, src);
        }
        CP_COMMIT();
    };

    // ldmatrix lane addressing
    const int a_row = lid & 15;            // + m tile base
    const int a_kof = (lid >> 4) * 8;      // 0 or 8
    const int b_row = lid & 7;
    const int b_kof = ((lid >> 3) & 1) * 8;

    load_chunk(0, 0);

    for (int kc = 0; kc < NC; kc++) {
        if (kc + 1 < NC) { load_chunk(kc + 1, (kc + 1) & 1); CP_WAIT(1); }
        else             { CP_WAIT(0); }
        __syncthreads();

        const uint32_t st = sbase + (kc & 1) * STAGEB;
        const uint32_t ah_b = st;
        const uint32_t al_b = st + PARTB;
        const uint32_t bh_b = st + 2 * PARTB;
        const uint32_t bl_b = st + 3 * PARTB;

#pragma unroll
        for (int ks = 0; ks < 2; ks++) {
            const int k0 = ks * 16;
            uint32_t ahf[4][4], alf[4][4], bhf[4][2], blf[4][2];
#pragma unroll
            for (int mi = 0; mi < 4; mi++) {
                int row = wm * 64 + mi * 16 + a_row;
                uint32_t off = row * ROWB + (k0 + a_kof) * 2;
                ldm_x4(ahf[mi], ah_b + off);
                ldm_x4(alf[mi], al_b + off);
            }
#pragma unroll
            for (int ni = 0; ni < 4; ni++) {
                int row = wn * 32 + ni * 8 + b_row;
                uint32_t off = row * ROWB + (k0 + b_kof) * 2;
                ldm_x2(bhf[ni], bh_b + off);
                ldm_x2(blf[ni], bl_b + off);
            }
#pragma unroll
            for (int mi = 0; mi < 4; mi++)
#pragma unroll
                for (int ni = 0; ni < 4; ni++) {
                    mma_bf16(acc[mi][ni], ahf[mi], bhf[ni]);
                    mma_bf16(acc[mi][ni], ahf[mi], blf[ni]);
                    mma_bf16(acc[mi][ni], alf[mi], bhf[ni]);
                }
        }
        __syncthreads();
    }

    // ---- epilogue (register accumulators -> gmem, fused) ----
    const int r_in = lid >> 2;       // 0..7
    const int c_in = (lid & 3) * 2;  // 0,2,4,6
#pragma unroll
    for (int mi = 0; mi < 4; mi++) {
#pragma unroll
        for (int ni = 0; ni < 4; ni++) {
            int row0 = brow + wm * 64 + mi * 16 + r_in;
            int col  = bcol + wn * 32 + ni * 8 + c_in;
            float2 bv = *(const float2*)&bias[col];
            float v[4];
            v[0] = acc[mi][ni][0] + bv.x;
            v[1] = acc[mi][ni][1] + bv.y;
            v[2] = acc[mi][ni][2] + bv.x;
            v[3] = acc[mi][ni][3] + bv.y;
            size_t i0 = (size_t)row0 * N + col;
            size_t i1 = (size_t)(row0 + 8) * N + col;
            if (epi == 1) {
#pragma unroll
                for (int e = 0; e < 4; e++)
                    v[e] = 0.5f * v[e] * (1.f + erff(v[e] * 0.70710678118654752f));
                __nv_bfloat16 h0,l0,h1,l1;
                split2(v[0], h0, l0); split2(v[1], h1, l1);
                *(__nv_bfloat162*)&Ch[i0] = __nv_bfloat162(h0, h1);
                *(__nv_bfloat162*)&Cl[i0] = __nv_bfloat162(l0, l1);
                split2(v[2], h0, l0); split2(v[3], h1, l1);
                *(__nv_bfloat162*)&Ch[i1] = __nv_bfloat162(h0, h1);
                *(__nv_bfloat162*)&Cl[i1] = __nv_bfloat162(l0, l1);
            } else {
                if (epi == 2) {
                    float2 r0 = *(const float2*)&Res[i0];
                    float2 r1 = *(const float2*)&Res[i1];
                    v[0] += r0.x; v[1] += r0.y; v[2] += r1.x; v[3] += r1.y;
                }
                *(float2*)&Cf[i0] = make_float2(v[0], v[1]);
                *(float2*)&Cf[i1] = make_float2(v[2], v[3]);
            }
        }
    }
}

// ======================= fused flash attention (fp32) =======================
#define ATT_SMEM_FLOATS (64*64 + 64*64 + 64*68)
#define ATT_SMEM_BYTES  (ATT_SMEM_FLOATS * 4)

__global__ __launch_bounds__(256, 2)
void attention_kernel(const float* __restrict__ Qg, const float* __restrict__ Kg,
                      const float* __restrict__ Vg,
                      __nv_bfloat16* __restrict__ Oh, __nv_bfloat16* __restrict__ Ol)
{
    extern __shared__ float sm[];
    float* Qs  = sm;
    float* Ps  = sm + 4096;
    float* KVs = sm + 8192;

    const int tid = threadIdx.x;
    const int qt  = blockIdx.x;
    const int bh  = blockIdx.y;
    const int b_  = bh >> 4;
    const int h_  = bh & 15;
    const int LDQ = QKV_N;

    const size_t baseQ  = ((size_t)(b_ * SEQ + qt * 64)) * LDQ + h_ * DH;
    const size_t baseKV = ((size_t)(b_ * SEQ)) * LDQ + h_ * DH;

    for (int i = tid; i < 1024; i += 256) {
        int r = i >> 4, c4 = (i & 15) * 4;
        *(float4*)(Qs + r * 64 + c4) = *(const float4*)(Qg + baseQ + (size_t)r * LDQ + c4);
    }

    const int qi = (tid >> 4) * 4;
    const int kj = (tid & 15) * 4;

    float m_i[4], l_i[4], acc[4][4];
#pragma unroll
    for (int i = 0; i < 4; i++) {
        m_i[i] = -INFINITY; l_i[i] = 0.f;
#pragma unroll
        for (int j = 0; j < 4; j++) acc[i][j] = 0.f;
    }

    for (int kt = 0; kt < 32; kt++) {
        __syncthreads();
        for (int i = tid; i < 1024; i += 256) {
            int r = i >> 4, c4 = (i & 15) * 4;
            *(float4*)(KVs + r * 68 + c4) =
                *(const float4*)(Kg + baseKV + (size_t)(kt * 64 + r) * LDQ + c4);
        }
        __syncthreads();

        float s[4][4];
#pragma unroll
        for (int i = 0; i < 4; i++)
#pragma unroll
            for (int j = 0; j < 4; j++) s[i][j] = 0.f;

#pragma unroll
        for (int d = 0; d < 64; d += 4) {
            float4 a[4], bv[4];
#pragma unroll
            for (int i = 0; i < 4; i++) a[i]  = *(float4*)(Qs  + (qi + i) * 64 + d);
#pragma unroll
            for (int j = 0; j < 4; j++) bv[j] = *(float4*)(KVs + (kj + j) * 68 + d);
#pragma unroll
            for (int i = 0; i < 4; i++)
#pragma unroll
                for (int j = 0; j < 4; j++)
                    s[i][j] += a[i].x*bv[j].x + a[i].y*bv[j].y + a[i].z*bv[j].z + a[i].w*bv[j].w;
        }

#pragma unroll
        for (int i = 0; i < 4; i++) {
            float mx = -INFINITY;
#pragma unroll
            for (int j = 0; j < 4; j++) { s[i][j] *= 0.125f; mx = fmaxf(mx, s[i][j]); }
#pragma unroll
            for (int o = 8; o >= 1; o >>= 1) mx = fmaxf(mx, __shfl_xor_sync(0xffffffffu, mx, o));
            float mnew = fmaxf(m_i[i], mx);
            float f    = __expf(m_i[i] - mnew);
            float rs   = 0.f;
#pragma unroll
            for (int j = 0; j < 4; j++) { float p = __expf(s[i][j] - mnew); s[i][j] = p; rs += p; }
#pragma unroll
            for (int o = 8; o >= 1; o >>= 1) rs += __shfl_xor_sync(0xffffffffu, rs, o);
            l_i[i] = l_i[i] * f + rs;
            m_i[i] = mnew;
#pragma unroll
            for (int j = 0; j < 4; j++) acc[i][j] *= f;
        }

#pragma unroll
        for (int i = 0; i < 4; i++)
            *(float4*)(Ps + (qi + i) * 64 + kj) = make_float4(s[i][0], s[i][1], s[i][2], s[i][3]);
        __syncthreads();

        for (int i = tid; i < 1024; i += 256) {
            int r = i >> 4, c4 = (i & 15) * 4;
            *(float4*)(KVs + r * 68 + c4) =
                *(const float4*)(Vg + baseKV + (size_t)(kt * 64 + r) * LDQ + c4);
        }
        __syncthreads();

#pragma unroll
        for (int k = 0; k < 64; k += 4) {
            float4 a[4];
#pragma unroll
            for (int i = 0; i < 4; i++) a[i] = *(float4*)(Ps + (qi + i) * 64 + k);
#pragma unroll
            for (int kk = 0; kk < 4; kk++) {
                float4 bv = *(float4*)(KVs + (k + kk) * 68 + kj);
#pragma unroll
                for (int i = 0; i < 4; i++) {
                    float av = (kk == 0) ? a[i].x : (kk == 1) ? a[i].y : (kk == 2) ? a[i].z : a[i].w;
                    acc[i][0] += av * bv.x;
                    acc[i][1] += av * bv.y;
                    acc[i][2] += av * bv.z;
                    acc[i][3] += av * bv.w;
                }
            }
        }
    }

#pragma unroll
    for (int i = 0; i < 4; i++) {
        float inv = 1.f / l_i[i];
        size_t o = ((size_t)(b_ * SEQ + qt * 64 + qi + i)) * D_MODEL + h_ * DH + kj;
        __nv_bfloat16 h0,l0,h1,l1,h2,l2,h3,l3;
        split2(acc[i][0]*inv, h0, l0); split2(acc[i][1]*inv, h1, l1);
        split2(acc[i][2]*inv, h2, l2); split2(acc[i][3]*inv, h3, l3);
        *(__nv_bfloat162*)(Oh + o)     = __nv_bfloat162(h0, h1);
        *(__nv_bfloat162*)(Oh + o + 2) = __nv_bfloat162(h2, h3);
        *(__nv_bfloat162*)(Ol + o)     = __nv_bfloat162(l0, l1);
        *(__nv_bfloat162*)(Ol + o + 2) = __nv_bfloat162(l2, l3);
    }
}

// ======================= layernorm ==========================================
__global__ void layernorm_kernel(const float* __restrict__ in, const float* __restrict__ g,
                                 const float* __restrict__ be, float* __restrict__ out,
                                 __nv_bfloat16* __restrict__ oh, __nv_bfloat16* __restrict__ ol,
                                 int transpose_out)
{
    __shared__ float rs[8], rq[8];
    const int row = blockIdx.x;
    const int tid = threadIdx.x;

    float4 v = ((const float4*)(in + (size_t)row * D_MODEL))[tid];
    float s = v.x + v.y + v.z + v.w;
    float q = v.x*v.x + v.y*v.y + v.z*v.z + v.w*v.w;
#pragma unroll
    for (int o = 16; o >= 1; o >>= 1) {
        s += __shfl_xor_sync(0xffffffffu, s, o);
        q += __shfl_xor_sync(0xffffffffu, q, o);
    }
    if ((tid & 31) == 0) { rs[tid >> 5] = s; rq[tid >> 5] = q; }
    __syncthreads();
    s = 0.f; q = 0.f;
#pragma unroll
    for (int i = 0; i < 8; i++) { s += rs[i]; q += rq[i]; }

    float mean = s * (1.f / D_MODEL);
    float var  = q * (1.f / D_MODEL) - mean * mean;
    float rstd = rsqrtf(var + EPS);

    float4 g4 = ((const float4*)g)[tid];
    float4 b4 = ((const float4*)be)[tid];
    float4 o4;
    o4.x = (v.x - mean) * rstd * g4.x + b4.x;
    o4.y = (v.y - mean) * rstd * g4.y + b4.y;
    o4.z = (v.z - mean) * rstd * g4.z + b4.z;
    o4.w = (v.w - mean) * rstd * g4.w + b4.w;

    size_t orow = row;
    if (transpose_out) {
        int b_ = row >> 11;
        int s_ = row & 2047;
        orow = (size_t)s_ * BATCH + b_;
    }
    ((float4*)(out + orow * D_MODEL))[tid] = o4;

    if (oh) {
        __nv_bfloat16 h0,l0,h1,l1,h2,l2,h3,l3;
        split2(o4.x,h0,l0); split2(o4.y,h1,l1); split2(o4.z,h2,l2); split2(o4.w,h3,l3);
        size_t o = (size_t)row * D_MODEL + tid * 4;
        *(__nv_bfloat162*)(oh + o)     = __nv_bfloat162(h0, h1);
        *(__nv_bfloat162*)(oh + o + 2) = __nv_bfloat162(h2, h3);
        *(__nv_bfloat162*)(ol + o)     = __nv_bfloat162(l0, l1);
        *(__nv_bfloat162*)(ol + o + 2) = __nv_bfloat162(l2, l3);
    }
}

// ======================= launch =============================================
extern "C" void kernel_launch(void* const* d_in, const int* in_sizes, int n_in,
                              void* d_out, int out_size)
{
    const float* x   = (const float*)d_in[0];
    const float* Wq  = (const float*)d_in[1];
    const float* bq  = (const float*)d_in[2];
    const float* Wk  = (const float*)d_in[3];
    const float* bk  = (const float*)d_in[4];
    const float* Wv  = (const float*)d_in[5];
    const float* bv  = (const float*)d_in[6];
    const float* Wo  = (const float*)d_in[7];
    const float* bo  = (const float*)d_in[8];
    const float* W1  = (const float*)d_in[9];
    const float* b1  = (const float*)d_in[10];
    const float* W2  = (const float*)d_in[11];
    const float* b2  = (const float*)d_in[12];
    const float* g1  = (const float*)d_in[13];
    const float* be1 = (const float*)d_in[14];
    const float* g2  = (const float*)d_in[15];
    const float* be2 = (const float*)d_in[16];
    float* out = (float*)d_out;

    float *XB, *QKV, *T1, *X1, *T2, *bqkv;
    __nv_bfloat16 *XBh, *XBl, *CTXh, *CTXl, *X1h, *X1l, *Hh, *Hl;
    __nv_bfloat16 *Wqkvth, *Wqkvtl, *Woth, *Wotl, *W1th, *W1tl, *W2th, *W2tl;
    cudaGetSymbolAddress((void**)&XB,   g_XB);
    cudaGetSymbolAddress((void**)&XBh,  g_XBh);
    cudaGetSymbolAddress((void**)&XBl,  g_XBl);
    cudaGetSymbolAddress((void**)&QKV,  g_QKV);
    cudaGetSymbolAddress((void**)&CTXh, g_CTXh);
    cudaGetSymbolAddress((void**)&CTXl, g_CTXl);
    cudaGetSymbolAddress((void**)&T1,   g_T1);
    cudaGetSymbolAddress((void**)&X1,   g_X1);
    cudaGetSymbolAddress((void**)&X1h,  g_X1h);
    cudaGetSymbolAddress((void**)&X1l,  g_X1l);
    cudaGetSymbolAddress((void**)&Hh,   g_Hh);
    cudaGetSymbolAddress((void**)&Hl,   g_Hl);
    cudaGetSymbolAddress((void**)&T2,   g_T2);
    cudaGetSymbolAddress((void**)&Wqkvth, g_Wqkvth);
    cudaGetSymbolAddress((void**)&Wqkvtl, g_Wqkvtl);
    cudaGetSymbolAddress((void**)&Woth, g_Woth);
    cudaGetSymbolAddress((void**)&Wotl, g_Wotl);
    cudaGetSymbolAddress((void**)&W1th, g_W1th);
    cudaGetSymbolAddress((void**)&W1tl, g_W1tl);
    cudaGetSymbolAddress((void**)&W2th, g_W2th);
    cudaGetSymbolAddress((void**)&W2tl, g_W2tl);
    cudaGetSymbolAddress((void**)&bqkv, g_bqkv);

    cudaFuncSetAttribute(gemm_hmma_kernel, cudaFuncAttributeMaxDynamicSharedMemorySize, GEMM_SMEM);
    cudaFuncSetAttribute(attention_kernel, cudaFuncAttributeMaxDynamicSharedMemorySize, ATT_SMEM_BYTES);

    // prep
    transpose_in_kernel<<<4096, 256>>>(x, XB, XBh, XBl);
    dim3 tsb(32, 8);
    transpose_split_kernel<<<dim3(D_MODEL/32, D_MODEL/32), tsb>>>(Wq, D_MODEL, D_MODEL, Wqkvth, Wqkvtl);
    transpose_split_kernel<<<dim3(D_MODEL/32, D_MODEL/32), tsb>>>(Wk, D_MODEL, D_MODEL,
        Wqkvth + (size_t)D_MODEL*D_MODEL, Wqkvtl + (size_t)D_MODEL*D_MODEL);
    transpose_split_kernel<<<dim3(D_MODEL/32, D_MODEL/32), tsb>>>(Wv, D_MODEL, D_MODEL,
        Wqkvth + (size_t)2*D_MODEL*D_MODEL, Wqkvtl + (size_t)2*D_MODEL*D_MODEL);
    transpose_split_kernel<<<dim3(D_MODEL/32, D_MODEL/32), tsb>>>(Wo, D_MODEL, D_MODEL, Woth, Wotl);
    transpose_split_kernel<<<dim3(D_FF/32,    D_MODEL/32), tsb>>>(W1, D_MODEL, D_FF,   W1th, W1tl);
    transpose_split_kernel<<<dim3(D_MODEL/32, D_FF/32),    tsb>>>(W2, D_FF,    D_MODEL, W2th, W2tl);
    concat_bias_kernel<<<(QKV_N + 255)/256, 256>>>(bq, bk, bv, bqkv);

    // fused QKV: [4096, 3072]
    gemm_hmma_kernel<<<dim3(QKV_N/128, NTOK/128), 256, GEMM_SMEM>>>(
        XBh, XBl, Wqkvth, Wqkvtl, bqkv, nullptr, QKV, nullptr, nullptr, D_MODEL, QKV_N, 0);

    // attention -> CTX hi/lo
    attention_kernel<<<dim3(SEQ/64, BATCH*NHEAD), 256, ATT_SMEM_BYTES>>>(
        QKV, QKV + D_MODEL, QKV + 2*D_MODEL, CTXh, CTXl);

    // O-proj + residual -> T1 ; LN1 -> X1 (+hi/lo)
    gemm_hmma_kernel<<<dim3(D_MODEL/128, NTOK/128), 256, GEMM_SMEM>>>(
        CTXh, CTXl, Woth, Wotl, bo, XB, T1, nullptr, nullptr, D_MODEL, D_MODEL, 2);
    layernorm_kernel<<<NTOK, 256>>>(T1, g1, be1, X1, X1h, X1l, 0);

    // FFN1 (+GELU) -> H hi/lo
    gemm_hmma_kernel<<<dim3(D_FF/128, NTOK/128), 256, GEMM_SMEM>>>(
        X1h, X1l, W1th, W1tl, b1, nullptr, nullptr, Hh, Hl, D_MODEL, D_FF, 1);

    // FFN2 + residual -> T2 ; LN2 -> out (transposed)
    gemm_hmma_kernel<<<dim3(D_MODEL/128, NTOK/128), 256, GEMM_SMEM>>>(
        Hh, Hl, W2th, W2tl, b2, X1, T2, nullptr, nullptr, D_FF, D_MODEL, 2);
    layernorm_kernel<<<NTOK, 256>>>(T2, g2, be2, out, nullptr, nullptr, 1);
}

// round 4
// speedup vs baseline: 3.3241x; 2.0983x over previous
#include <cuda_runtime.h>
#include <cuda_bf16.h>
#include <cuda.h>
#include <math.h>
#include <stdint.h>

#define D_MODEL 1024
#define NHEAD   16
#define DH      64
#define D_FF    4096
#define SEQ     2048
#define BATCH   2
#define NTOK    (SEQ * BATCH)
#define EPS     1e-5f
#define QKV_N   (3 * D_MODEL)   // 3072

// ======================= helpers ============================================
__device__ __forceinline__ uint32_t smem_to_u32(const void* p) {
    uint32_t a;
    asm("{ .reg .u64 t; cvta.to.shared.u64 t, %1; cvt.u32.u64 %0, t; }" : "=r"(a) : "l"(p));
    return a;
}
__device__ __forceinline__ void cp_async16(uint32_t dst, const void* src) {
    asm volatile("cp.async.cg.shared.global [%0], [%1], 16;" :: "r"(dst), "l"(src) : "memory");
}
#define CP_COMMIT() asm volatile("cp.async.commit_group;" ::: "memory")
#define CP_WAIT(n)  asm volatile("cp.async.wait_group %0;" :: "n"(n) : "memory")

__device__ __forceinline__ void ldm_x4(uint32_t* r, uint32_t addr) {
    asm volatile("ldmatrix.sync.aligned.m8n8.x4.shared.b16 {%0,%1,%2,%3}, [%4];"
        : "=r"(r[0]), "=r"(r[1]), "=r"(r[2]), "=r"(r[3]) : "r"(addr));
}
__device__ __forceinline__ void ldm_x4_t(uint32_t* r, uint32_t addr) {
    asm volatile("ldmatrix.sync.aligned.m8n8.x4.trans.shared.b16 {%0,%1,%2,%3}, [%4];"
        : "=r"(r[0]), "=r"(r[1]), "=r"(r[2]), "=r"(r[3]) : "r"(addr));
}
__device__ __forceinline__ void ldm_x2(uint32_t* r, uint32_t addr) {
    asm volatile("ldmatrix.sync.aligned.m8n8.x2.shared.b16 {%0,%1}, [%2];"
        : "=r"(r[0]), "=r"(r[1]) : "r"(addr));
}
__device__ __forceinline__ void mma_bf16(float* d, const uint32_t* a, const uint32_t* b) {
    asm volatile("mma.sync.aligned.m16n8k16.row.col.f32.bf16.bf16.f32 "
        "{%0,%1,%2,%3}, {%4,%5,%6,%7}, {%8,%9}, {%0,%1,%2,%3};"
        : "+f"(d[0]), "+f"(d[1]), "+f"(d[2]), "+f"(d[3])
        : "r"(a[0]), "r"(a[1]), "r"(a[2]), "r"(a[3]), "r"(b[0]), "r"(b[1]));
}
__device__ __forceinline__ void split2(float x, __nv_bfloat16& h, __nv_bfloat16& l) {
    h = __float2bfloat16_rn(x);
    l = __float2bfloat16_rn(x - __bfloat162float(h));
}
__device__ __forceinline__ uint32_t pk(__nv_bfloat16 a, __nv_bfloat16 b) {
    __nv_bfloat162 t(a, b);
    return *reinterpret_cast<uint32_t*>(&t);
}

// ======================= scratch ============================================
__device__ float          g_XB  [NTOK * D_MODEL];
__device__ __nv_bfloat16  g_XBh [NTOK * D_MODEL];
__device__ __nv_bfloat16  g_XBl [NTOK * D_MODEL];
__device__ __nv_bfloat16  g_QKVh[NTOK * QKV_N];
__device__ __nv_bfloat16  g_QKVl[NTOK * QKV_N];
__device__ __nv_bfloat16  g_CTXh[NTOK * D_MODEL];
__device__ __nv_bfloat16  g_CTXl[NTOK * D_MODEL];
__device__ float          g_T1  [NTOK * D_MODEL];
__device__ float          g_X1  [NTOK * D_MODEL];
__device__ __nv_bfloat16  g_X1h [NTOK * D_MODEL];
__device__ __nv_bfloat16  g_X1l [NTOK * D_MODEL];
__device__ __nv_bfloat16  g_Hh  [NTOK * D_FF];
__device__ __nv_bfloat16  g_Hl  [NTOK * D_FF];
__device__ float          g_T2  [NTOK * D_MODEL];
__device__ __nv_bfloat16  g_Wqkvth[QKV_N * D_MODEL];
__device__ __nv_bfloat16  g_Wqkvtl[QKV_N * D_MODEL];
__device__ __nv_bfloat16  g_Woth[D_MODEL * D_MODEL];
__device__ __nv_bfloat16  g_Wotl[D_MODEL * D_MODEL];
__device__ __nv_bfloat16  g_W1th[D_FF * D_MODEL];
__device__ __nv_bfloat16  g_W1tl[D_FF * D_MODEL];
__device__ __nv_bfloat16  g_W2th[D_MODEL * D_FF];
__device__ __nv_bfloat16  g_W2tl[D_MODEL * D_FF];
__device__ float          g_bqkv[QKV_N];

// ======================= prep kernels =======================================
__global__ void transpose_in_kernel(const float* __restrict__ x, float* __restrict__ xb,
                                    __nv_bfloat16* __restrict__ xh, __nv_bfloat16* __restrict__ xl)
{
    int idx = blockIdx.x * 256 + threadIdx.x;
    int r  = idx >> 8;
    int c4 = idx & 255;
    int b_ = r / SEQ;
    int s_ = r - b_ * SEQ;
    float4 v = ((const float4*)x)[(size_t)(s_ * BATCH + b_) * 256 + c4];
    ((float4*)xb)[idx] = v;
    __nv_bfloat16 h0,l0,h1,l1,h2,l2,h3,l3;
    split2(v.x,h0,l0); split2(v.y,h1,l1); split2(v.z,h2,l2); split2(v.w,h3,l3);
    __nv_bfloat162* ph = (__nv_bfloat162*)(xh + (size_t)idx * 4);
    __nv_bfloat162* pl = (__nv_bfloat162*)(xl + (size_t)idx * 4);
    ph[0] = __nv_bfloat162(h0, h1); ph[1] = __nv_bfloat162(h2, h3);
    pl[0] = __nv_bfloat162(l0, l1); pl[1] = __nv_bfloat162(l2, l3);
}

__global__ void transpose_split_kernel(const float* __restrict__ W, int K, int N,
                                       __nv_bfloat16* __restrict__ Oh, __nv_bfloat16* __restrict__ Ol)
{
    __shared__ float t[32][33];
    int n0 = blockIdx.x * 32, k0 = blockIdx.y * 32;
    int tx = threadIdx.x, ty = threadIdx.y;     // (32, 8)
#pragma unroll
    for (int i = 0; i < 4; i++)
        t[ty + 8*i][tx] = W[(size_t)(k0 + ty + 8*i) * N + n0 + tx];
    __syncthreads();
#pragma unroll
    for (int i = 0; i < 4; i++) {
        float v = t[tx][ty + 8*i];
        __nv_bfloat16 h, l; split2(v, h, l);
        size_t o = (size_t)(n0 + ty + 8*i) * K + k0 + tx;
        Oh[o] = h; Ol[o] = l;
    }
}

__global__ void concat_bias_kernel(const float* bq, const float* bk, const float* bv, float* o)
{
    int i = blockIdx.x * 256 + threadIdx.x;
    if (i < QKV_N) {
        const float* s = (i < 1024) ? bq : (i < 2048) ? bk : bv;
        o[i] = s[i & 1023];
    }
}

// ======================= HMMA bf16x3 GEMM ===================================
// epi 0: +bias -> Cf ; 1: +bias,GELU -> Ch,Cl ; 2: +bias +Res -> Cf ; 3: +bias -> Ch,Cl
#define GK        32
#define ROWB      80
#define PARTB     (128 * ROWB)
#define STAGEB    (4 * PARTB)
#define GEMM_SMEM (2 * STAGEB)

__global__ __launch_bounds__(256)
void gemm_hmma_kernel(const __nv_bfloat16* __restrict__ Ah, const __nv_bfloat16* __restrict__ Al,
                      const __nv_bfloat16* __restrict__ Bth, const __nv_bfloat16* __restrict__ Btl,
                      const float* __restrict__ bias, const float* __restrict__ Res,
                      float* __restrict__ Cf, __nv_bfloat16* __restrict__ Ch, __nv_bfloat16* __restrict__ Cl,
                      int K, int N, int epi)
{
    extern __shared__ char smem[];
    const uint32_t sbase = smem_to_u32(smem);

    const int tid = threadIdx.x;
    const int wid = tid >> 5;
    const int lid = tid & 31;
    const int wm = wid >> 2;
    const int wn = wid & 3;
    const int brow = blockIdx.y * 128;
    const int bcol = blockIdx.x * 128;
    const int NC = K / GK;

    float acc[4][4][4];
#pragma unroll
    for (int mi = 0; mi < 4; mi++)
#pragma unroll
        for (int ni = 0; ni < 4; ni++)
#pragma unroll
            for (int e = 0; e < 4; e++) acc[mi][ni][e] = 0.f;

    auto load_chunk = [&](int kc, int s) {
        const int kb = kc * GK;
        const __nv_bfloat16* srcs[4] = { Ah, Al, Bth, Btl };
#pragma unroll
        for (int p = 0; p < 8; p++) {
            int i = tid + p * 256;
            int part = i >> 9;
            int j = i & 511;
            int r = j >> 2, c = j & 3;
            int grow = ((part < 2) ? brow : bcol) + r;
            const __nv_bfloat16* src = srcs[part] + (size_t)grow * K + kb + c * 8;
            cp_async16(sbase + s * STAGEB + part * PARTB + r * ROWB + c * 16, src);
        }
        CP_COMMIT();
    };

    const int a_row = lid & 15;
    const int a_kof = (lid >> 4) * 8;
    const int b_row = lid & 7;
    const int b_kof = ((lid >> 3) & 1) * 8;

    load_chunk(0, 0);

    for (int kc = 0; kc < NC; kc++) {
        if (kc + 1 < NC) { load_chunk(kc + 1, (kc + 1) & 1); CP_WAIT(1); }
        else             { CP_WAIT(0); }
        __syncthreads();

        const uint32_t st = sbase + (kc & 1) * STAGEB;
        const uint32_t ah_b = st;
        const uint32_t al_b = st + PARTB;
        const uint32_t bh_b = st + 2 * PARTB;
        const uint32_t bl_b = st + 3 * PARTB;

#pragma unroll
        for (int ks = 0; ks < 2; ks++) {
            const int k0 = ks * 16;
            uint32_t ahf[4][4], alf[4][4], bhf[4][2], blf[4][2];
#pragma unroll
            for (int mi = 0; mi < 4; mi++) {
                int row = wm * 64 + mi * 16 + a_row;
                uint32_t off = row * ROWB + (k0 + a_kof) * 2;
                ldm_x4(ahf[mi], ah_b + off);
                ldm_x4(alf[mi], al_b + off);
            }
#pragma unroll
            for (int ni = 0; ni < 4; ni++) {
                int row = wn * 32 + ni * 8 + b_row;
                uint32_t off = row * ROWB + (k0 + b_kof) * 2;
                ldm_x2(bhf[ni], bh_b + off);
                ldm_x2(blf[ni], bl_b + off);
            }
#pragma unroll
            for (int mi = 0; mi < 4; mi++)
#pragma unroll
                for (int ni = 0; ni < 4; ni++) {
                    mma_bf16(acc[mi][ni], ahf[mi], bhf[ni]);
                    mma_bf16(acc[mi][ni], ahf[mi], blf[ni]);
                    mma_bf16(acc[mi][ni], alf[mi], bhf[ni]);
                }
        }
        __syncthreads();
    }

    const int r_in = lid >> 2;
    const int c_in = (lid & 3) * 2;
#pragma unroll
    for (int mi = 0; mi < 4; mi++) {
#pragma unroll
        for (int ni = 0; ni < 4; ni++) {
            int row0 = brow + wm * 64 + mi * 16 + r_in;
            int col  = bcol + wn * 32 + ni * 8 + c_in;
            float2 bv = *(const float2*)&bias[col];
            float v[4];
            v[0] = acc[mi][ni][0] + bv.x;
            v[1] = acc[mi][ni][1] + bv.y;
            v[2] = acc[mi][ni][2] + bv.x;
            v[3] = acc[mi][ni][3] + bv.y;
            size_t i0 = (size_t)row0 * N + col;
            size_t i1 = (size_t)(row0 + 8) * N + col;
            if (epi == 1 || epi == 3) {
                if (epi == 1) {
#pragma unroll
                    for (int e = 0; e < 4; e++)
                        v[e] = 0.5f * v[e] * (1.f + erff(v[e] * 0.70710678118654752f));
                }
                __nv_bfloat16 h0,l0,h1,l1;
                split2(v[0], h0, l0); split2(v[1], h1, l1);
                *(__nv_bfloat162*)&Ch[i0] = __nv_bfloat162(h0, h1);
                *(__nv_bfloat162*)&Cl[i0] = __nv_bfloat162(l0, l1);
                split2(v[2], h0, l0); split2(v[3], h1, l1);
                *(__nv_bfloat162*)&Ch[i1] = __nv_bfloat162(h0, h1);
                *(__nv_bfloat162*)&Cl[i1] = __nv_bfloat162(l0, l1);
            } else {
                if (epi == 2) {
                    float2 r0 = *(const float2*)&Res[i0];
                    float2 r1 = *(const float2*)&Res[i1];
                    v[0] += r0.x; v[1] += r0.y; v[2] += r1.x; v[3] += r1.y;
                }
                *(float2*)&Cf[i0] = make_float2(v[0], v[1]);
                *(float2*)&Cf[i1] = make_float2(v[2], v[3]);
            }
        }
    }
}

// ======================= HMMA flash attention ================================
// block = 128 q rows x one (b,h). 8 warps x 16 q rows. K tiles of 64 keys.
// 3-term bf16 splits on QK^T and PV. P stays in registers (C-frag == A-frag layout).
#define AP_B    144                    // smem row pitch bytes (64 bf16 + 16B pad)
#define Q_PART  (128 * AP_B)           // 18432
#define KV_PART (64 * AP_B)            // 9216
#define ATT_SMEM (2 * Q_PART + 8 * KV_PART)   // 110592

__global__ __launch_bounds__(256)
void attention_hmma_kernel(const __nv_bfloat16* __restrict__ QKVh,
                           const __nv_bfloat16* __restrict__ QKVl,
                           __nv_bfloat16* __restrict__ Oh, __nv_bfloat16* __restrict__ Ol)
{
    extern __shared__ char smem[];
    const uint32_t sbase = smem_to_u32(smem);
    const int tid = threadIdx.x, wid = tid >> 5, lid = tid & 31;
    const int qt = blockIdx.x, bh = blockIdx.y;
    const int b_ = bh >> 4, h_ = bh & 15;
    const int qrow0 = b_ * SEQ + qt * 128;
    const int krow0 = b_ * SEQ;
    const size_t LDQ = QKV_N;

    // Q tile (hi+lo) -> smem
    {
        const __nv_bfloat16* srcs[2] = { QKVh, QKVl };
#pragma unroll
        for (int t = 0; t < 8; t++) {
            int i = tid + t * 256;
            int part = i >> 10, j = i & 1023, r = j >> 3, c = j & 7;
            cp_async16(sbase + part * Q_PART + r * AP_B + c * 16,
                       srcs[part] + (size_t)(qrow0 + r) * LDQ + h_ * 64 + c * 8);
        }
        CP_COMMIT();
    }
    auto load_kv = [&](int kt, int s) {
        const __nv_bfloat16* srcs[4] = { QKVh, QKVl, QKVh, QKVl };
        const int coff[4] = { 1024, 1024, 2048, 2048 };
#pragma unroll
        for (int t = 0; t < 8; t++) {
            int i = tid + t * 256;
            int part = i >> 9, j = i & 511, r = j >> 3, c = j & 7;
            cp_async16(sbase + 2 * Q_PART + s * (4 * KV_PART) + part * KV_PART + r * AP_B + c * 16,
                       srcs[part] + (size_t)(krow0 + kt * 64 + r) * LDQ + coff[part] + h_ * 64 + c * 8);
        }
        CP_COMMIT();
    };
    load_kv(0, 0);
    CP_WAIT(1);            // Q done (KV0 may be in flight)
    __syncthreads();

    // Q fragments (held in regs for the whole kernel)
    uint32_t aQh[4][4], aQl[4][4];
    {
        const int arow = lid & 15, akof = (lid >> 4) * 8;
#pragma unroll
        for (int ks = 0; ks < 4; ks++) {
            uint32_t off = (wid * 16 + arow) * AP_B + (ks * 16 + akof) * 2;
            ldm_x4(aQh[ks], sbase + off);
            ldm_x4(aQl[ks], sbase + Q_PART + off);
        }
    }

    float m0 = -INFINITY, m1 = -INFINITY, l0 = 0.f, l1 = 0.f;
    float oA[8][4];
#pragma unroll
    for (int ni = 0; ni < 8; ni++)
#pragma unroll
        for (int e = 0; e < 4; e++) oA[ni][e] = 0.f;

    const int bkey = (lid & 7) + 8 * (lid >> 4);        // K frag x4 lane row
    const int bkof = ((lid >> 3) & 1) * 8;              // K frag k offset
    const int vkey = (lid & 7) + 8 * ((lid >> 3) & 1);  // V trans frag lane row
    const int vdh  = (lid >> 4) * 8;                    // V trans frag dh offset

    for (int kt = 0; kt < 32; kt++) {
        if (kt < 31) { load_kv(kt + 1, (kt + 1) & 1); CP_WAIT(1); }
        else         { CP_WAIT(0); }
        __syncthreads();
        const uint32_t kb = sbase + 2 * Q_PART + (kt & 1) * (4 * KV_PART);

        // ---- scores S = Q K^T (3-term) ----
        float sc[8][4];
#pragma unroll
        for (int ni = 0; ni < 8; ni++)
#pragma unroll
            for (int e = 0; e < 4; e++) sc[ni][e] = 0.f;

#pragma unroll
        for (int ks = 0; ks < 4; ks++) {
#pragma unroll
            for (int nip = 0; nip < 4; nip++) {
                uint32_t off = (nip * 16 + bkey) * AP_B + (ks * 16 + bkof) * 2;
                uint32_t bh4[4], bl4[4];
                ldm_x4(bh4, kb + off);
                ldm_x4(bl4, kb + KV_PART + off);
                mma_bf16(sc[2*nip],   aQh[ks], bh4);
                mma_bf16(sc[2*nip+1], aQh[ks], bh4 + 2);
                mma_bf16(sc[2*nip],   aQh[ks], bl4);
                mma_bf16(sc[2*nip+1], aQh[ks], bl4 + 2);
                mma_bf16(sc[2*nip],   aQl[ks], bh4);
                mma_bf16(sc[2*nip+1], aQl[ks], bh4 + 2);
            }
        }

        // ---- online softmax (rows r_in and r_in+8) ----
        float mx0 = -INFINITY, mx1 = -INFINITY;
#pragma unroll
        for (int ni = 0; ni < 8; ni++) {
#pragma unroll
            for (int e = 0; e < 4; e++) sc[ni][e] *= 0.125f;
            mx0 = fmaxf(mx0, fmaxf(sc[ni][0], sc[ni][1]));
            mx1 = fmaxf(mx1, fmaxf(sc[ni][2], sc[ni][3]));
        }
        mx0 = fmaxf(mx0, __shfl_xor_sync(0xffffffffu, mx0, 1));
        mx0 = fmaxf(mx0, __shfl_xor_sync(0xffffffffu, mx0, 2));
        mx1 = fmaxf(mx1, __shfl_xor_sync(0xffffffffu, mx1, 1));
        mx1 = fmaxf(mx1, __shfl_xor_sync(0xffffffffu, mx1, 2));
        float mn0 = fmaxf(m0, mx0), mn1 = fmaxf(m1, mx1);
        float f0 = __expf(m0 - mn0), f1 = __expf(m1 - mn1);
        float r0 = 0.f, r1 = 0.f;
#pragma unroll
        for (int ni = 0; ni < 8; ni++) {
            sc[ni][0] = __expf(sc[ni][0] - mn0);
            sc[ni][1] = __expf(sc[ni][1] - mn0);
            sc[ni][2] = __expf(sc[ni][2] - mn1);
            sc[ni][3] = __expf(sc[ni][3] - mn1);
            r0 += sc[ni][0] + sc[ni][1];
            r1 += sc[ni][2] + sc[ni][3];
        }
        r0 += __shfl_xor_sync(0xffffffffu, r0, 1);
        r0 += __shfl_xor_sync(0xffffffffu, r0, 2);
        r1 += __shfl_xor_sync(0xffffffffu, r1, 1);
        r1 += __shfl_xor_sync(0xffffffffu, r1, 2);
        l0 = l0 * f0 + r0;  l1 = l1 * f1 + r1;
        m0 = mn0;           m1 = mn1;
#pragma unroll
        for (int ni = 0; ni < 8; ni++) {
            oA[ni][0] *= f0; oA[ni][1] *= f0;
            oA[ni][2] *= f1; oA[ni][3] *= f1;
        }

        // ---- PV: ctx += P V (3-term); P repacked from score regs ----
#pragma unroll
        for (int ks = 0; ks < 4; ks++) {
            uint32_t ah[4], al[4];
            {
                __nv_bfloat16 h, l;
                float p0 = sc[2*ks][0],   p1 = sc[2*ks][1];
                float p2 = sc[2*ks][2],   p3 = sc[2*ks][3];
                float p4 = sc[2*ks+1][0], p5 = sc[2*ks+1][1];
                float p6 = sc[2*ks+1][2], p7 = sc[2*ks+1][3];
                __nv_bfloat16 h0,l0b,h1,l1b;
                split2(p0,h0,l0b); split2(p1,h1,l1b); ah[0]=pk(h0,h1); al[0]=pk(l0b,l1b);
                split2(p2,h0,l0b); split2(p3,h1,l1b); ah[1]=pk(h0,h1); al[1]=pk(l0b,l1b);
                split2(p4,h0,l0b); split2(p5,h1,l1b); ah[2]=pk(h0,h1); al[2]=pk(l0b,l1b);
                split2(p6,h0,l0b); split2(p7,h1,l1b); ah[3]=pk(h0,h1); al[3]=pk(l0b,l1b);
                (void)h; (void)l;
            }
#pragma unroll
            for (int nip = 0; nip < 4; nip++) {
                uint32_t off = (ks * 16 + vkey) * AP_B + (nip * 16 + vdh) * 2;
                uint32_t vh4[4], vl4[4];
                ldm_x4_t(vh4, kb + 2 * KV_PART + off);
                ldm_x4_t(vl4, kb + 3 * KV_PART + off);
                mma_bf16(oA[2*nip],   ah, vh4);
                mma_bf16(oA[2*nip+1], ah, vh4 + 2);
                mma_bf16(oA[2*nip],   ah, vl4);
                mma_bf16(oA[2*nip+1], ah, vl4 + 2);
                mma_bf16(oA[2*nip],   al, vh4);
                mma_bf16(oA[2*nip+1], al, vh4 + 2);
            }
        }
        __syncthreads();
    }

    // ---- write ctx (bf16 hi/lo, [row][D_MODEL]) ----
    const float inv0 = 1.f / l0, inv1 = 1.f / l1;
    const int row0 = qrow0 + wid * 16 + (lid >> 2);
    const int colb = h_ * 64 + (lid & 3) * 2;
#pragma unroll
    for (int ni = 0; ni < 8; ni++) {
        int col = colb + ni * 8;
        __nv_bfloat16 h0,lo0,h1,lo1;
        split2(oA[ni][0] * inv0, h0, lo0);
        split2(oA[ni][1] * inv0, h1, lo1);
        size_t i0 = (size_t)row0 * D_MODEL + col;
        *(__nv_bfloat162*)&Oh[i0] = __nv_bfloat162(h0, h1);
        *(__nv_bfloat162*)&Ol[i0] = __nv_bfloat162(lo0, lo1);
        split2(oA[ni][2] * inv1, h0, lo0);
        split2(oA[ni][3] * inv1, h1, lo1);
        size_t i1 = (size_t)(row0 + 8) * D_MODEL + col;
        *(__nv_bfloat162*)&Oh[i1] = __nv_bfloat162(h0, h1);
        *(__nv_bfloat162*)&Ol[i1] = __nv_bfloat162(lo0, lo1);
    }
}

// ======================= layernorm ==========================================
__global__ void layernorm_kernel(const float* __restrict__ in, const float* __restrict__ g,
                                 const float* __restrict__ be, float* __restrict__ out,
                                 __nv_bfloat16* __restrict__ oh, __nv_bfloat16* __restrict__ ol,
                                 int transpose_out)
{
    __shared__ float rs[8], rq[8];
    const int row = blockIdx.x;
    const int tid = threadIdx.x;

    float4 v = ((const float4*)(in + (size_t)row * D_MODEL))[tid];
    float s = v.x + v.y + v.z + v.w;
    float q = v.x*v.x + v.y*v.y + v.z*v.z + v.w*v.w;
#pragma unroll
    for (int o = 16; o >= 1; o >>= 1) {
        s += __shfl_xor_sync(0xffffffffu, s, o);
        q += __shfl_xor_sync(0xffffffffu, q, o);
    }
    if ((tid & 31) == 0) { rs[tid >> 5] = s; rq[tid >> 5] = q; }
    __syncthreads();
    s = 0.f; q = 0.f;
#pragma unroll
    for (int i = 0; i < 8; i++) { s += rs[i]; q += rq[i]; }

    float mean = s * (1.f / D_MODEL);
    float var  = q * (1.f / D_MODEL) - mean * mean;
    float rstd = rsqrtf(var + EPS);

    float4 g4 = ((const float4*)g)[tid];
    float4 b4 = ((const float4*)be)[tid];
    float4 o4;
    o4.x = (v.x - mean) * rstd * g4.x + b4.x;
    o4.y = (v.y - mean) * rstd * g4.y + b4.y;
    o4.z = (v.z - mean) * rstd * g4.z + b4.z;
    o4.w = (v.w - mean) * rstd * g4.w + b4.w;

    size_t orow = row;
    if (transpose_out) {
        int b_ = row >> 11;
        int s_ = row & 2047;
        orow = (size_t)s_ * BATCH + b_;
    }
    ((float4*)(out + orow * D_MODEL))[tid] = o4;

    if (oh) {
        __nv_bfloat16 h0,l0,h1,l1,h2,l2,h3,l3;
        split2(o4.x,h0,l0); split2(o4.y,h1,l1); split2(o4.z,h2,l2); split2(o4.w,h3,l3);
        size_t o = (size_t)row * D_MODEL + tid * 4;
        *(__nv_bfloat162*)(oh + o)     = __nv_bfloat162(h0, h1);
        *(__nv_bfloat162*)(oh + o + 2) = __nv_bfloat162(h2, h3);
        *(__nv_bfloat162*)(ol + o)     = __nv_bfloat162(l0, l1);
        *(__nv_bfloat162*)(ol + o + 2) = __nv_bfloat162(l2, l3);
    }
}

// ======================= launch =============================================
extern "C" void kernel_launch(void* const* d_in, const int* in_sizes, int n_in,
                              void* d_out, int out_size)
{
    const float* x   = (const float*)d_in[0];
    const float* Wq  = (const float*)d_in[1];
    const float* bq  = (const float*)d_in[2];
    const float* Wk  = (const float*)d_in[3];
    const float* bk  = (const float*)d_in[4];
    const float* Wv  = (const float*)d_in[5];
    const float* bv  = (const float*)d_in[6];
    const float* Wo  = (const float*)d_in[7];
    const float* bo  = (const float*)d_in[8];
    const float* W1  = (const float*)d_in[9];
    const float* b1  = (const float*)d_in[10];
    const float* W2  = (const float*)d_in[11];
    const float* b2  = (const float*)d_in[12];
    const float* g1  = (const float*)d_in[13];
    const float* be1 = (const float*)d_in[14];
    const float* g2  = (const float*)d_in[15];
    const float* be2 = (const float*)d_in[16];
    float* out = (float*)d_out;

    float *XB, *T1, *X1, *T2, *bqkv;
    __nv_bfloat16 *XBh, *XBl, *QKVh, *QKVl, *CTXh, *CTXl, *X1h, *X1l, *Hh, *Hl;
    __nv_bfloat16 *Wqkvth, *Wqkvtl, *Woth, *Wotl, *W1th, *W1tl, *W2th, *W2tl;
    cudaGetSymbolAddress((void**)&XB,   g_XB);
    cudaGetSymbolAddress((void**)&XBh,  g_XBh);
    cudaGetSymbolAddress((void**)&XBl,  g_XBl);
    cudaGetSymbolAddress((void**)&QKVh, g_QKVh);
    cudaGetSymbolAddress((void**)&QKVl, g_QKVl);
    cudaGetSymbolAddress((void**)&CTXh, g_CTXh);
    cudaGetSymbolAddress((void**)&CTXl, g_CTXl);
    cudaGetSymbolAddress((void**)&T1,   g_T1);
    cudaGetSymbolAddress((void**)&X1,   g_X1);
    cudaGetSymbolAddress((void**)&X1h,  g_X1h);
    cudaGetSymbolAddress((void**)&X1l,  g_X1l);
    cudaGetSymbolAddress((void**)&Hh,   g_Hh);
    cudaGetSymbolAddress((void**)&Hl,   g_Hl);
    cudaGetSymbolAddress((void**)&T2,   g_T2);
    cudaGetSymbolAddress((void**)&Wqkvth, g_Wqkvth);
    cudaGetSymbolAddress((void**)&Wqkvtl, g_Wqkvtl);
    cudaGetSymbolAddress((void**)&Woth, g_Woth);
    cudaGetSymbolAddress((void**)&Wotl, g_Wotl);
    cudaGetSymbolAddress((void**)&W1th, g_W1th);
    cudaGetSymbolAddress((void**)&W1tl, g_W1tl);
    cudaGetSymbolAddress((void**)&W2th, g_W2th);
    cudaGetSymbolAddress((void**)&W2tl, g_W2tl);
    cudaGetSymbolAddress((void**)&bqkv, g_bqkv);

    cudaFuncSetAttribute(gemm_hmma_kernel, cudaFuncAttributeMaxDynamicSharedMemorySize, GEMM_SMEM);
    cudaFuncSetAttribute(attention_hmma_kernel, cudaFuncAttributeMaxDynamicSharedMemorySize, ATT_SMEM);

    // prep
    transpose_in_kernel<<<4096, 256>>>(x, XB, XBh, XBl);
    dim3 tsb(32, 8);
    transpose_split_kernel<<<dim3(D_MODEL/32, D_MODEL/32), tsb>>>(Wq, D_MODEL, D_MODEL, Wqkvth, Wqkvtl);
    transpose_split_kernel<<<dim3(D_MODEL/32, D_MODEL/32), tsb>>>(Wk, D_MODEL, D_MODEL,
        Wqkvth + (size_t)D_MODEL*D_MODEL, Wqkvtl + (size_t)D_MODEL*D_MODEL);
    transpose_split_kernel<<<dim3(D_MODEL/32, D_MODEL/32), tsb>>>(Wv, D_MODEL, D_MODEL,
        Wqkvth + (size_t)2*D_MODEL*D_MODEL, Wqkvtl + (size_t)2*D_MODEL*D_MODEL);
    transpose_split_kernel<<<dim3(D_MODEL/32, D_MODEL/32), tsb>>>(Wo, D_MODEL, D_MODEL, Woth, Wotl);
    transpose_split_kernel<<<dim3(D_FF/32,    D_MODEL/32), tsb>>>(W1, D_MODEL, D_FF,   W1th, W1tl);
    transpose_split_kernel<<<dim3(D_MODEL/32, D_FF/32),    tsb>>>(W2, D_FF,    D_MODEL, W2th, W2tl);
    concat_bias_kernel<<<(QKV_N + 255)/256, 256>>>(bq, bk, bv, bqkv);

    // fused QKV -> bf16 hi/lo (epi 3)
    gemm_hmma_kernel<<<dim3(QKV_N/128, NTOK/128), 256, GEMM_SMEM>>>(
        XBh, XBl, Wqkvth, Wqkvtl, bqkv, nullptr, nullptr, QKVh, QKVl, D_MODEL, QKV_N, 3);

    // HMMA flash attention -> CTX hi/lo
    attention_hmma_kernel<<<dim3(SEQ/128, BATCH*NHEAD), 256, ATT_SMEM>>>(QKVh, QKVl, CTXh, CTXl);

    // O-proj + residual -> T1 ; LN1 -> X1 (+hi/lo)
    gemm_hmma_kernel<<<dim3(D_MODEL/128, NTOK/128), 256, GEMM_SMEM>>>(
        CTXh, CTXl, Woth, Wotl, bo, XB, T1, nullptr, nullptr, D_MODEL, D_MODEL, 2);
    layernorm_kernel<<<NTOK, 256>>>(T1, g1, be1, X1, X1h, X1l, 0);

    // FFN1 (+GELU) -> H hi/lo
    gemm_hmma_kernel<<<dim3(D_FF/128, NTOK/128), 256, GEMM_SMEM>>>(
        X1h, X1l, W1th, W1tl, b1, nullptr, nullptr, Hh, Hl, D_MODEL, D_FF, 1);

    // FFN2 + residual -> T2 ; LN2 -> out (transposed)
    gemm_hmma_kernel<<<dim3(D_MODEL/128, NTOK/128), 256, GEMM_SMEM>>>(
        Hh, Hl, W2th, W2tl, b2, X1, T2, nullptr, nullptr, D_FF, D_MODEL, 2);
    layernorm_kernel<<<NTOK, 256>>>(T2, g2, be2, out, nullptr, nullptr, 1);
}